// round 12
// baseline (speedup 1.0000x reference)
#include <cuda_runtime.h>
#include <math.h>

#define HIDC   128
#define NHEADS 3
#define OPHC   43
#define MIDC   129   // NHEADS*OPHC
#define OUTC   6
#define MAXN   50000
#define MAXEDG 850000
#define LDH    132   // padded row stride for g_h/g_y (16B aligned rows)
#define KT     32
#define WPAD   132
#define ECH    64    // edge chunk per warp in k_agg_big
#define WSTR   65    // head-stride in smem weight array (bank-skewed)

// ---------------- device scratch ----------------
__device__ float g_h  [MAXN * LDH];
__device__ float g_y  [MAXN * LDH];
__device__ float g_al4[MAXN * 4];
__device__ float g_ar4[MAXN * 4];
__device__ int   g_counts [MAXN];      // degree counts, then fill-cursor; re-zeroed each pass
__device__ int   g_offsets[MAXN + 1];  // block-local exclusive scan
__device__ int   g_blk [64];
__device__ int   g_pre [66];           // block prefix table (+ total)
__device__ int   g_done;
__device__ int   g_csr[MAXEDG];

__device__ __forceinline__ float lrelu(float x) { return x >= 0.0f ? x : 0.2f * x; }
__device__ __forceinline__ float pick3(float a0, float a1, float a2, int i) {
    return i == 0 ? a0 : (i == 1 ? a1 : a2);
}

// packed f32x2 helpers (sm_103a FFMA2 path)
__device__ __forceinline__ unsigned long long pack2(float a, float b) {
    unsigned long long r;
    asm("mov.b64 %0, {%1, %2};" : "=l"(r) : "f"(a), "f"(b));
    return r;
}
__device__ __forceinline__ void unpack2(unsigned long long v, float& a, float& b) {
    asm("mov.b64 {%0, %1}, %2;" : "=f"(a), "=f"(b) : "l"(v));
}
__device__ __forceinline__ void ffma2(unsigned long long& d, unsigned long long a,
                                      unsigned long long b) {
    asm("fma.rn.f32x2 %0, %1, %2, %0;" : "+l"(d) : "l"(a), "l"(b));
}

// per-block edge-index dtype probe: odd 32-bit words of first 64 elems all zero -> int64
__device__ __forceinline__ int block_is64(const unsigned int* w) {
    unsigned int v = (threadIdx.x < 64) ? w[2 * threadIdx.x + 1] : 0u;
    int any = __syncthreads_or(v != 0u);
    return any == 0;
}

__device__ __forceinline__ int load_idx(const void* ei, int is64, long long i, int n) {
    int v;
    if (is64) v = (int)((const long long*)ei)[i];
    else      v = ((const int*)ei)[i];
    v = v < 0 ? 0 : (v >= n ? n - 1 : v);
    return v;
}

// ---------------- shared GEMM body (CO = 129), 8 rows per warp ----------------
// Weights staged INTERLEAVED: sW[l*WPAD + 4*lane + {0,1,2,3}] = W[l][{2l',2l'+1,64+2l',65+2l'}]
// so one LDS.128 fetches both column-pair weights. Col 128 kept at sW[l*WPAD+128].
#define GBODY8(LL)                                                                   \
    {                                                                                \
        const float* xp = sAw + (LL) * 8;                                            \
        float4 xlo = *(const float4*)xp;                                             \
        float4 xhi = *(const float4*)(xp + 4);                                       \
        ulonglong2 wp = *(const ulonglong2*)(sW + (LL) * WPAD + 4 * lane);           \
        unsigned long long X;                                                        \
        X = pack2(xlo.x, xlo.x); ffma2(acc[0][0], X, wp.x); ffma2(acc[0][1], X, wp.y); \
        X = pack2(xlo.y, xlo.y); ffma2(acc[1][0], X, wp.x); ffma2(acc[1][1], X, wp.y); \
        X = pack2(xlo.z, xlo.z); ffma2(acc[2][0], X, wp.x); ffma2(acc[2][1], X, wp.y); \
        X = pack2(xlo.w, xlo.w); ffma2(acc[3][0], X, wp.x); ffma2(acc[3][1], X, wp.y); \
        X = pack2(xhi.x, xhi.x); ffma2(acc[4][0], X, wp.x); ffma2(acc[4][1], X, wp.y); \
        X = pack2(xhi.y, xhi.y); ffma2(acc[5][0], X, wp.x); ffma2(acc[5][1], X, wp.y); \
        X = pack2(xhi.z, xhi.z); ffma2(acc[6][0], X, wp.x); ffma2(acc[6][1], X, wp.y); \
        X = pack2(xhi.w, xhi.w); ffma2(acc[7][0], X, wp.x); ffma2(acc[7][1], X, wp.y); \
    }

__device__ __forceinline__ void gemm_body(const float* __restrict__ A,
                                          const float* __restrict__ W,
                                          const float* __restrict__ as_,
                                          const float* __restrict__ ad_,
                                          int nrows, int CI, int lda, int leakyIn)
{
    __shared__ __align__(16) float sW[KT * WPAD];
    __shared__ __align__(16) float sA[8][KT * 8];

    int lane = threadIdx.x & 31;
    int warp = threadIdx.x >> 5;
    int r0   = (blockIdx.x * 8 + warp) * 8;
    float* sAw = sA[warp];

    unsigned long long acc[8][2];
    float acc128[8];
#pragma unroll
    for (int r = 0; r < 8; ++r) { acc[r][0] = 0ull; acc[r][1] = 0ull; acc128[r] = 0.0f; }

    for (int kbase = 0; kbase < CI; kbase += KT) {
        int kmax = CI - kbase; if (kmax > KT) kmax = KT;
        __syncthreads();
        // interleaved weight staging
        for (int i = threadIdx.x; i < kmax * WPAD; i += 256) {
            int kr = i / WPAD, cc = i - kr * WPAD;
            int src;
            if (cc < 128) {
                int ln = cc >> 2, j = cc & 3;
                src = (j < 2) ? (2 * ln + j) : (62 + 2 * ln + j);
            } else {
                src = cc;   // 128 valid; 129..131 padded
            }
            sW[i] = (src < MIDC) ? W[(size_t)(kbase + kr) * MIDC + src] : 0.0f;
        }
        {
            int kcol = kbase + lane;
            bool kok = kcol < CI;
            float av[8];
#pragma unroll
            for (int r = 0; r < 8; ++r) {
                int row = r0 + r;
                float v = (kok && row < nrows) ? A[(size_t)row * lda + kcol] : 0.0f;
                av[r] = leakyIn ? lrelu(v) : v;
            }
            *(float4*)(sAw + lane * 8)     = make_float4(av[0], av[1], av[2], av[3]);
            *(float4*)(sAw + lane * 8 + 4) = make_float4(av[4], av[5], av[6], av[7]);
        }
        __syncthreads();

        if (r0 < nrows) {
#pragma unroll 16
            for (int l = 0; l < kmax; ++l) GBODY8(l)
            if (lane < kmax) {
                float w128 = sW[lane * WPAD + 128];
                const float* xp = sAw + lane * 8;
#pragma unroll
                for (int r = 0; r < 8; ++r) acc128[r] += xp[r] * w128;
            }
        }
    }

    if (r0 >= nrows) return;

#pragma unroll
    for (int r = 0; r < 8; ++r)
#pragma unroll
        for (int off = 16; off; off >>= 1)
            acc128[r] += __shfl_xor_sync(0xffffffffu, acc128[r], off);

    int  cols[4] = { 2 * lane, 2 * lane + 1, 64 + 2 * lane, 65 + 2 * lane };
    float asv[4], adv[4];
    int   hd[4];
#pragma unroll
    for (int j = 0; j < 4; ++j) {
        asv[j] = as_[cols[j]];
        adv[j] = ad_[cols[j]];
        hd[j]  = cols[j] / OPHC;
    }
    float as128 = as_[128], ad128 = ad_[128];

#pragma unroll
    for (int r = 0; r < 8; ++r) {
        int row = r0 + r;
        if (row >= nrows) break;
        float vv[4];
        unpack2(acc[r][0], vv[0], vv[1]);
        unpack2(acc[r][1], vv[2], vv[3]);
        float c128 = acc128[r];

        float sl0 = 0, sl1 = 0, sl2 = 0, sr0 = 0, sr1 = 0, sr2 = 0;
#pragma unroll
        for (int j = 0; j < 4; ++j) {
            float s = asv[j] * vv[j], d = adv[j] * vv[j];
            if      (hd[j] == 0) { sl0 += s; sr0 += d; }
            else if (hd[j] == 1) { sl1 += s; sr1 += d; }
            else                 { sl2 += s; sr2 += d; }
        }
#pragma unroll
        for (int off = 16; off; off >>= 1) {
            sl0 += __shfl_xor_sync(0xffffffffu, sl0, off);
            sr0 += __shfl_xor_sync(0xffffffffu, sr0, off);
            sl1 += __shfl_xor_sync(0xffffffffu, sl1, off);
            sr1 += __shfl_xor_sync(0xffffffffu, sr1, off);
            sl2 += __shfl_xor_sync(0xffffffffu, sl2, off);
            sr2 += __shfl_xor_sync(0xffffffffu, sr2, off);
        }
        sl2 += as128 * c128;
        sr2 += ad128 * c128;
        if (lane == 0) {
            *(float4*)(g_al4 + 4 * row) = make_float4(sl0, sl1, sl2, 0.0f);
            *(float4*)(g_ar4 + 4 * row) = make_float4(sr0, sr1, sr2, 0.0f);
        }
        float* hp = g_h + (size_t)row * LDH;
        *(float2*)(hp + 2 * lane)      = make_float2(vv[0], vv[1]);
        *(float2*)(hp + 64 + 2 * lane) = make_float2(vv[2], vv[3]);
        if (lane == 0) hp[128] = c128;
    }
}

// ---------------- launch 1: layer-0 GEMM + edge counting (spare blocks) ----------------
__global__ void __launch_bounds__(256) k_gemm0_count(
    const float* __restrict__ x, const float* __restrict__ W0,
    const float* __restrict__ a0s, const float* __restrict__ a0d,
    int nrows, const void* __restrict__ ei, int E, int gemmBlocks)
{
    if ((int)blockIdx.x < gemmBlocks) {
        gemm_body(x, W0, a0s, a0d, nrows, HIDC, HIDC, 0);
    } else {
        int is64 = block_is64((const unsigned int*)ei);
        int tot = E + nrows;
        int base = ((int)blockIdx.x - gemmBlocks) * 256 + threadIdx.x;
        int stride = ((int)gridDim.x - gemmBlocks) * 256;
        for (int e = base; e < tot; e += stride) {
            int d = (e < E) ? load_idx(ei, is64, (long long)E + e, nrows) : (e - E);
            atomicAdd(&g_counts[d], 1);
        }
    }
}

// ---------------- launch 2: single-pass scan ----------------
__global__ void k_scan(int nb, int n) {
    __shared__ int sh[1024];
    int t = threadIdx.x;
    int i = blockIdx.x * 1024 + t;
    int v = 0;
    if (i < n) { v = g_counts[i]; g_counts[i] = 0; }
    sh[t] = v;
    __syncthreads();
    for (int off = 1; off < 1024; off <<= 1) {
        int tv = (t >= off) ? sh[t - off] : 0;
        __syncthreads();
        sh[t] += tv;
        __syncthreads();
    }
    if (i <= n) g_offsets[i] = sh[t] - v;
    if (t == 1023) {
        g_blk[blockIdx.x] = sh[1023];
        __threadfence();
        if (atomicAdd(&g_done, 1) == (int)gridDim.x - 1) {
            int run = 0;
            for (int j = 0; j < nb; ++j) {
                g_pre[j] = run;
                run += atomicAdd(&g_blk[j], 0);
            }
            g_pre[nb] = run;
            g_done = 0;
        }
    }
}

// ---------------- launch 3: CSR fill ----------------
__global__ void k_fill(const void* __restrict__ ei, int E, int n) {
    int is64 = block_is64((const unsigned int*)ei);
    int tot = E + n;
    for (int e = blockIdx.x * blockDim.x + threadIdx.x; e < tot; e += gridDim.x * blockDim.x) {
        int s, d;
        if (e < E) {
            s = load_idx(ei, is64, e, n);
            d = load_idx(ei, is64, (long long)E + e, n);
        } else {
            s = e - E; d = s;
        }
        int pos = g_offsets[d] + g_pre[d >> 10] + atomicAdd(&g_counts[d], 1);
        if (pos < MAXEDG) g_csr[pos] = s;
    }
}

// ---------------- big aggregation (CO=129, 3 heads), one warp per dst node ----------------
// Phase 1 (lane-parallel): exps into head-major smem (stride 65, bank-skewed) +
// byte offsets + col-128 accumulation. Phase 2: pure weighted gather —
// per edge: 5 LDS + LDG.128 + 2 pack + 2 FFMA2, zero selects, no MUFU.
__global__ void __launch_bounds__(128) k_agg_big(const float* __restrict__ bias, int n)
{
    __shared__ float s_w  [4][3 * WSTR + 1];
    __shared__ int   s_off[4][ECH];

    int warp = threadIdx.x >> 5;
    int lane = threadIdx.x & 31;
    int node = blockIdx.x * 4 + warp;
    if (node >= n) return;

    int s0 = g_offsets[node]     + g_pre[node >> 10];
    int s1 = g_offsets[node + 1] + g_pre[(node + 1) >> 10];
    int deg = s1 - s0;
    if (lane == 0) g_counts[node] = 0;      // reset fill-cursor for next replay

    float4 arn = *(const float4*)(g_ar4 + 4 * node);
    float* sw  = s_w[warp];
    int*   soff = s_off[warp];

    // lane-constant weight pointers: col c0+j reads sw[hj*WSTR + i]
    int c0 = 4 * lane;
    const float* pw0 = sw + (c0 / OPHC) * WSTR;
    const float* pw1 = sw + ((c0 + 1) / OPHC) * WSTR;
    const float* pw2 = sw + ((c0 + 2) / OPHC) * WSTR;
    const float* pw3 = sw + ((c0 + 3) / OPHC) * WSTR;
    const char*  hbase = (const char*)g_h + (size_t)c0 * 4;

    unsigned long long acc01 = 0ull, acc23 = 0ull;
    float acc128 = 0.0f;
    float d0 = 0.0f, d1 = 0.0f, d2 = 0.0f;

    for (int base = 0; base < deg; base += ECH) {
        int m = deg - base; if (m > ECH) m = ECH;

        // phase 1: exps + offsets + col128 (lane-strided)
        for (int i = lane; i < m; i += 32) {
            int src = g_csr[s0 + base + i];
            float4 a = *(const float4*)(g_al4 + 4 * src);
            float e0 = __expf(fminf(lrelu(a.x + arn.x), 80.0f));
            float e1 = __expf(fminf(lrelu(a.y + arn.y), 80.0f));
            float e2 = __expf(fminf(lrelu(a.z + arn.z), 80.0f));
            d0 += e0; d1 += e1; d2 += e2;
            sw[i]            = e0;
            sw[WSTR + i]     = e1;
            sw[2 * WSTR + i] = e2;
            soff[i] = src * (LDH * 4);
            acc128 += e2 * g_h[(size_t)src * LDH + 128];
        }
        __syncwarp();

        // phase 2: weighted gather
#pragma unroll 4
        for (int i = 0; i < m; ++i) {
            int off = soff[i];
            float4 hv = *(const float4*)(hbase + off);
            float w0 = pw0[i], w1 = pw1[i], w2 = pw2[i], w3 = pw3[i];
            ffma2(acc01, pack2(w0, w1), pack2(hv.x, hv.y));
            ffma2(acc23, pack2(w2, w3), pack2(hv.z, hv.w));
        }
        __syncwarp();
    }

    // reductions: denominators + col128
#pragma unroll
    for (int off = 16; off; off >>= 1) {
        d0     += __shfl_xor_sync(0xffffffffu, d0, off);
        d1     += __shfl_xor_sync(0xffffffffu, d1, off);
        d2     += __shfl_xor_sync(0xffffffffu, d2, off);
        acc128 += __shfl_xor_sync(0xffffffffu, acc128, off);
    }
    float i0 = 1.0f / (d0 + 1e-16f);
    float i1 = 1.0f / (d1 + 1e-16f);
    float i2 = 1.0f / (d2 + 1e-16f);

    float ix = pick3(i0, i1, i2, c0 / OPHC);
    float iy = pick3(i0, i1, i2, (c0 + 1) / OPHC);
    float iz = pick3(i0, i1, i2, (c0 + 2) / OPHC);
    float iw = pick3(i0, i1, i2, (c0 + 3) / OPHC);

    float ax, ay, az, aw;
    unpack2(acc01, ax, ay);
    unpack2(acc23, az, aw);

    float* op = g_y + (size_t)node * LDH;
    float4 b4 = *(const float4*)(bias + c0);
    float4 o;
    o.x = ax * ix + b4.x;
    o.y = ay * iy + b4.y;
    o.z = az * iz + b4.z;
    o.w = aw * iw + b4.w;
    *(float4*)(op + c0) = o;
    if (lane == 0) op[128] = acc128 * i2 + bias[128];
}

// ---------------- layer-1 GEMM ----------------
__global__ void __launch_bounds__(256) k_gemm_big(
    const float* __restrict__ W, const float* __restrict__ as_,
    const float* __restrict__ ad_, int nrows)
{
    gemm_body((const float*)g_y, W, as_, ad_, nrows, MIDC, LDH, 1);
}

// ---------------- small GEMM (layer 2, CO=6) + fused attention ----------------
__global__ void k_gemm_small(const float* __restrict__ W, const float* __restrict__ as_,
                             const float* __restrict__ ad_, int nrows)
{
    __shared__ float sW[MIDC * 9];
    for (int i = threadIdx.x; i < MIDC * 9; i += blockDim.x) {
        int k = i / 9, c = i - k * 9;
        sW[i] = (c < OUTC) ? W[k * OUTC + c] : 0.0f;
    }
    __syncthreads();

    int lane = threadIdx.x & 31;
    int warp = threadIdx.x >> 5;
    int row  = blockIdx.x * 8 + warp;
    if (row >= nrows) return;

    float acc[6] = {0, 0, 0, 0, 0, 0};
#pragma unroll
    for (int j = 0; j < 5; ++j) {
        int k = lane + 32 * j;
        if (k < MIDC) {
            float xv = lrelu(g_y[(size_t)row * LDH + k]);
            const float* wr = sW + k * 9;
#pragma unroll
            for (int cc = 0; cc < 6; ++cc) acc[cc] += xv * wr[cc];
        }
    }
#pragma unroll
    for (int off = 16; off; off >>= 1)
#pragma unroll
        for (int cc = 0; cc < 6; ++cc)
            acc[cc] += __shfl_xor_sync(0xffffffffu, acc[cc], off);

    if (lane == 0) {
        float al = 0, ar = 0;
        float* hp = g_h + (size_t)row * LDH;
#pragma unroll
        for (int cc = 0; cc < 6; ++cc) {
            al += acc[cc] * as_[cc];
            ar += acc[cc] * ad_[cc];
            hp[cc] = acc[cc];
        }
        *(float4*)(g_al4 + 4 * row) = make_float4(al, 0.0f, 0.0f, 0.0f);
        *(float4*)(g_ar4 + 4 * row) = make_float4(ar, 0.0f, 0.0f, 0.0f);
    }
}

// ---------------- small aggregation (CO=6, 1 head), 4 nodes per warp ----------------
__global__ void k_agg_small(const float* __restrict__ bias, float* __restrict__ dout, int n)
{
    int gw   = (int)((blockIdx.x * blockDim.x + threadIdx.x) >> 5);
    int lane = threadIdx.x & 31;
    int node = gw * 4 + (lane >> 3);
    int sub  = lane & 7;
    if (node >= n) return;

    int s0 = g_offsets[node]     + g_pre[node >> 10];
    int s1 = g_offsets[node + 1] + g_pre[(node + 1) >> 10];
    float arn = g_ar4[4 * node];

    float acc = 0.0f, den = 0.0f;
#pragma unroll 4
    for (int e = s0; e < s1; ++e) {
        int src = g_csr[e];
        float a = g_al4[4 * src];
        float e0 = __expf(fminf(lrelu(a + arn), 80.0f));
        den += e0;
        float hv = (sub < 6) ? g_h[(size_t)src * LDH + sub] : 0.0f;
        acc += e0 * hv;
    }
    if (sub < 6) dout[(size_t)node * OUTC + sub] = acc / (den + 1e-16f) + bias[sub];
}

// ---------------- launcher ----------------
extern "C" void kernel_launch(void* const* d_in, const int* in_sizes, int n_in,
                              void* d_out, int out_size)
{
    const float* x   = (const float*)d_in[0];
    const void*  ei  = d_in[1];
    const float* W0  = (const float*)d_in[2];
    const float* a0s = (const float*)d_in[3];
    const float* a0d = (const float*)d_in[4];
    const float* b0  = (const float*)d_in[5];
    const float* W1  = (const float*)d_in[6];
    const float* a1s = (const float*)d_in[7];
    const float* a1d = (const float*)d_in[8];
    const float* b1  = (const float*)d_in[9];
    const float* W2  = (const float*)d_in[10];
    const float* a2s = (const float*)d_in[11];
    const float* a2d = (const float*)d_in[12];
    const float* b2  = (const float*)d_in[13];

    int N = in_sizes[0] / HIDC;
    int E = in_sizes[1] / 2;

    int tot = E + N;
    int scan_blocks = (N + 1023) / 1024;
    int gemm_grid = (N + 63) / 64;    // 8 warps * 8 rows
    int agg_grid  = (N + 3) / 4;      // 4 warps, 1 node/warp
    int node_grid = (N + 7) / 8;      // 8 warps, 1 node/warp (small kernels)
    int count_blocks = 512;

    // 1: layer-0 GEMM (+attention epilogue) fused with edge counting
    k_gemm0_count<<<gemm_grid + count_blocks, 256>>>(x, W0, a0s, a0d, N, ei, E, gemm_grid);
    // 2: single-pass scan
    k_scan<<<scan_blocks, 1024>>>(scan_blocks, N);
    // 3: CSR fill
    k_fill<<<(tot + 255) / 256, 256>>>(ei, E, N);
    // 4: layer-0 aggregation  <- profiled
    k_agg_big<<<agg_grid, 128>>>(b0, N);
    // 5: layer-1 GEMM
    k_gemm_big<<<gemm_grid, 256>>>(W1, a1s, a1d, N);
    // 6: layer-1 aggregation
    k_agg_big<<<agg_grid, 128>>>(b1, N);
    // 7: layer-2 GEMM
    k_gemm_small<<<node_grid, 256>>>(W2, a2s, a2d, N);
    // 8: layer-2 aggregation
    k_agg_small<<<(N + 31) / 32, 256>>>(b2, (float*)d_out, N);
}

// round 13
// speedup vs baseline: 1.2735x; 1.2735x over previous
#include <cuda_runtime.h>
#include <math.h>

#define HIDC   128
#define NHEADS 3
#define OPHC   43
#define MIDC   129   // NHEADS*OPHC
#define OUTC   6
#define MAXN   50000
#define MAXEDG 850000
#define LDH    132   // padded row stride for g_h/g_y (16B aligned rows)
#define KT     32
#define WPAD   132
#define ECH    64    // edge chunk per warp in k_agg_big
#define WSTR   65    // head-stride in smem weight array (bank-skewed)

// ---------------- device scratch ----------------
__device__ float g_h  [MAXN * LDH];
__device__ float g_y  [MAXN * LDH];
__device__ float g_al4[MAXN * 4];
__device__ float g_ar4[MAXN * 4];
__device__ int   g_counts [MAXN];      // degree counts, then fill-cursor; re-zeroed each pass
__device__ int   g_offsets[MAXN + 1];  // block-local exclusive scan
__device__ int   g_blk [64];
__device__ int   g_pre [66];           // block prefix table (+ total)
__device__ int   g_done;
__device__ int   g_csr[MAXEDG];

__device__ __forceinline__ float lrelu(float x) { return x >= 0.0f ? x : 0.2f * x; }
__device__ __forceinline__ float pick3(float a0, float a1, float a2, int i) {
    return i == 0 ? a0 : (i == 1 ? a1 : a2);
}

// packed f32x2 helpers (sm_103a FFMA2 path)
__device__ __forceinline__ unsigned long long pack2(float a, float b) {
    unsigned long long r;
    asm("mov.b64 %0, {%1, %2};" : "=l"(r) : "f"(a), "f"(b));
    return r;
}
__device__ __forceinline__ void unpack2(unsigned long long v, float& a, float& b) {
    asm("mov.b64 {%0, %1}, %2;" : "=f"(a), "=f"(b) : "l"(v));
}
__device__ __forceinline__ void ffma2(unsigned long long& d, unsigned long long a,
                                      unsigned long long b) {
    asm("fma.rn.f32x2 %0, %1, %2, %0;" : "+l"(d) : "l"(a), "l"(b));
}

// per-block edge-index dtype probe: odd 32-bit words of first 64 elems all zero -> int64
__device__ __forceinline__ int block_is64(const unsigned int* w) {
    unsigned int v = (threadIdx.x < 64) ? w[2 * threadIdx.x + 1] : 0u;
    int any = __syncthreads_or(v != 0u);
    return any == 0;
}

__device__ __forceinline__ int load_idx(const void* ei, int is64, long long i, int n) {
    int v;
    if (is64) v = (int)((const long long*)ei)[i];
    else      v = ((const int*)ei)[i];
    v = v < 0 ? 0 : (v >= n ? n - 1 : v);
    return v;
}

// ---------------- shared GEMM body (CO = 129), 8 rows per warp ----------------
#define GBODY8(LL)                                                                   \
    {                                                                                \
        const float* xp = sAw + (LL) * 8;                                            \
        float4 xlo = *(const float4*)xp;                                             \
        float4 xhi = *(const float4*)(xp + 4);                                       \
        const float* wr = sW + (LL) * WPAD + 2 * lane;                               \
        unsigned long long w0 = *(const unsigned long long*)wr;                      \
        unsigned long long w1 = *(const unsigned long long*)(wr + 64);               \
        unsigned long long X;                                                        \
        X = pack2(xlo.x, xlo.x); ffma2(acc[0][0], X, w0); ffma2(acc[0][1], X, w1);   \
        X = pack2(xlo.y, xlo.y); ffma2(acc[1][0], X, w0); ffma2(acc[1][1], X, w1);   \
        X = pack2(xlo.z, xlo.z); ffma2(acc[2][0], X, w0); ffma2(acc[2][1], X, w1);   \
        X = pack2(xlo.w, xlo.w); ffma2(acc[3][0], X, w0); ffma2(acc[3][1], X, w1);   \
        X = pack2(xhi.x, xhi.x); ffma2(acc[4][0], X, w0); ffma2(acc[4][1], X, w1);   \
        X = pack2(xhi.y, xhi.y); ffma2(acc[5][0], X, w0); ffma2(acc[5][1], X, w1);   \
        X = pack2(xhi.z, xhi.z); ffma2(acc[6][0], X, w0); ffma2(acc[6][1], X, w1);   \
        X = pack2(xhi.w, xhi.w); ffma2(acc[7][0], X, w0); ffma2(acc[7][1], X, w1);   \
    }

__device__ __forceinline__ void gemm_body(const float* __restrict__ A,
                                          const float* __restrict__ W,
                                          const float* __restrict__ as_,
                                          const float* __restrict__ ad_,
                                          int nrows, int CI, int lda, int leakyIn)
{
    __shared__ float sW[KT * WPAD];
    __shared__ __align__(16) float sA[8][KT * 8];

    int lane = threadIdx.x & 31;
    int warp = threadIdx.x >> 5;
    int r0   = (blockIdx.x * 8 + warp) * 8;
    float* sAw = sA[warp];

    unsigned long long acc[8][2];
    float acc128[8];
#pragma unroll
    for (int r = 0; r < 8; ++r) { acc[r][0] = 0ull; acc[r][1] = 0ull; acc128[r] = 0.0f; }

    for (int kbase = 0; kbase < CI; kbase += KT) {
        int kmax = CI - kbase; if (kmax > KT) kmax = KT;
        __syncthreads();
        for (int i = threadIdx.x; i < kmax * WPAD; i += 256) {
            int kr = i / WPAD, cc = i - kr * WPAD;
            sW[i] = (cc < MIDC) ? W[(size_t)(kbase + kr) * MIDC + cc] : 0.0f;
        }
        {
            int kcol = kbase + lane;
            bool kok = kcol < CI;
            float av[8];
#pragma unroll
            for (int r = 0; r < 8; ++r) {
                int row = r0 + r;
                float v = (kok && row < nrows) ? A[(size_t)row * lda + kcol] : 0.0f;
                av[r] = leakyIn ? lrelu(v) : v;
            }
            *(float4*)(sAw + lane * 8)     = make_float4(av[0], av[1], av[2], av[3]);
            *(float4*)(sAw + lane * 8 + 4) = make_float4(av[4], av[5], av[6], av[7]);
        }
        __syncthreads();

        if (r0 < nrows) {
#pragma unroll 16
            for (int l = 0; l < kmax; ++l) GBODY8(l)
            if (lane < kmax) {
                float w128 = sW[lane * WPAD + 128];
                const float* xp = sAw + lane * 8;
#pragma unroll
                for (int r = 0; r < 8; ++r) acc128[r] += xp[r] * w128;
            }
        }
    }

    if (r0 >= nrows) return;

#pragma unroll
    for (int r = 0; r < 8; ++r)
#pragma unroll
        for (int off = 16; off; off >>= 1)
            acc128[r] += __shfl_xor_sync(0xffffffffu, acc128[r], off);

    int  cols[4] = { 2 * lane, 2 * lane + 1, 64 + 2 * lane, 65 + 2 * lane };
    float asv[4], adv[4];
    int   hd[4];
#pragma unroll
    for (int j = 0; j < 4; ++j) {
        asv[j] = as_[cols[j]];
        adv[j] = ad_[cols[j]];
        hd[j]  = cols[j] / OPHC;
    }
    float as128 = as_[128], ad128 = ad_[128];

#pragma unroll
    for (int r = 0; r < 8; ++r) {
        int row = r0 + r;
        if (row >= nrows) break;
        float vv[4];
        unpack2(acc[r][0], vv[0], vv[1]);
        unpack2(acc[r][1], vv[2], vv[3]);
        float c128 = acc128[r];

        float sl0 = 0, sl1 = 0, sl2 = 0, sr0 = 0, sr1 = 0, sr2 = 0;
#pragma unroll
        for (int j = 0; j < 4; ++j) {
            float s = asv[j] * vv[j], d = adv[j] * vv[j];
            if      (hd[j] == 0) { sl0 += s; sr0 += d; }
            else if (hd[j] == 1) { sl1 += s; sr1 += d; }
            else                 { sl2 += s; sr2 += d; }
        }
#pragma unroll
        for (int off = 16; off; off >>= 1) {
            sl0 += __shfl_xor_sync(0xffffffffu, sl0, off);
            sr0 += __shfl_xor_sync(0xffffffffu, sr0, off);
            sl1 += __shfl_xor_sync(0xffffffffu, sl1, off);
            sr1 += __shfl_xor_sync(0xffffffffu, sr1, off);
            sl2 += __shfl_xor_sync(0xffffffffu, sl2, off);
            sr2 += __shfl_xor_sync(0xffffffffu, sr2, off);
        }
        sl2 += as128 * c128;
        sr2 += ad128 * c128;
        if (lane == 0) {
            *(float4*)(g_al4 + 4 * row) = make_float4(sl0, sl1, sl2, 0.0f);
            *(float4*)(g_ar4 + 4 * row) = make_float4(sr0, sr1, sr2, 0.0f);
        }
        float* hp = g_h + (size_t)row * LDH;
        *(float2*)(hp + 2 * lane)      = make_float2(vv[0], vv[1]);
        *(float2*)(hp + 64 + 2 * lane) = make_float2(vv[2], vv[3]);
        if (lane == 0) hp[128] = c128;
    }
}

// ---------------- launch 1: layer-0 GEMM + edge counting (spare blocks) ----------------
__global__ void __launch_bounds__(256, 4) k_gemm0_count(
    const float* __restrict__ x, const float* __restrict__ W0,
    const float* __restrict__ a0s, const float* __restrict__ a0d,
    int nrows, const void* __restrict__ ei, int E, int gemmBlocks)
{
    if ((int)blockIdx.x < gemmBlocks) {
        gemm_body(x, W0, a0s, a0d, nrows, HIDC, HIDC, 0);
    } else {
        int is64 = block_is64((const unsigned int*)ei);
        int tot = E + nrows;
        int base = ((int)blockIdx.x - gemmBlocks) * 256 + threadIdx.x;
        int stride = ((int)gridDim.x - gemmBlocks) * 256;
        for (int e = base; e < tot; e += stride) {
            int d = (e < E) ? load_idx(ei, is64, (long long)E + e, nrows) : (e - E);
            atomicAdd(&g_counts[d], 1);
        }
    }
}

// ---------------- launch 2: single-pass scan ----------------
__global__ void k_scan(int nb, int n) {
    __shared__ int sh[1024];
    int t = threadIdx.x;
    int i = blockIdx.x * 1024 + t;
    int v = 0;
    if (i < n) { v = g_counts[i]; g_counts[i] = 0; }
    sh[t] = v;
    __syncthreads();
    for (int off = 1; off < 1024; off <<= 1) {
        int tv = (t >= off) ? sh[t - off] : 0;
        __syncthreads();
        sh[t] += tv;
        __syncthreads();
    }
    if (i <= n) g_offsets[i] = sh[t] - v;
    if (t == 1023) {
        g_blk[blockIdx.x] = sh[1023];
        __threadfence();
        if (atomicAdd(&g_done, 1) == (int)gridDim.x - 1) {
            int run = 0;
            for (int j = 0; j < nb; ++j) {
                g_pre[j] = run;
                run += atomicAdd(&g_blk[j], 0);
            }
            g_pre[nb] = run;
            g_done = 0;
        }
    }
}

// ---------------- launch 3: CSR fill ----------------
__global__ void k_fill(const void* __restrict__ ei, int E, int n) {
    int is64 = block_is64((const unsigned int*)ei);
    int tot = E + n;
    for (int e = blockIdx.x * blockDim.x + threadIdx.x; e < tot; e += gridDim.x * blockDim.x) {
        int s, d;
        if (e < E) {
            s = load_idx(ei, is64, e, n);
            d = load_idx(ei, is64, (long long)E + e, n);
        } else {
            s = e - E; d = s;
        }
        int pos = g_offsets[d] + g_pre[d >> 10] + atomicAdd(&g_counts[d], 1);
        if (pos < MAXEDG) g_csr[pos] = s;
    }
}

// ---------------- big aggregation (CO=129, 3 heads), one warp per dst node ----------------
// Phase 1 (lane-parallel): exps into head-major smem (stride 65, bank-skewed) +
// byte offsets + col-128 accumulation. Phase 2: pure weighted gather —
// per edge: 5 LDS + LDG.128 + 2 pack + 2 FFMA2, zero selects, no MUFU.
__global__ void __launch_bounds__(128) k_agg_big(const float* __restrict__ bias, int n)
{
    __shared__ float s_w  [4][3 * WSTR + 1];
    __shared__ int   s_off[4][ECH];

    int warp = threadIdx.x >> 5;
    int lane = threadIdx.x & 31;
    int node = blockIdx.x * 4 + warp;
    if (node >= n) return;

    int s0 = g_offsets[node]     + g_pre[node >> 10];
    int s1 = g_offsets[node + 1] + g_pre[(node + 1) >> 10];
    int deg = s1 - s0;
    if (lane == 0) g_counts[node] = 0;      // reset fill-cursor for next replay

    float4 arn = *(const float4*)(g_ar4 + 4 * node);
    float* sw  = s_w[warp];
    int*   soff = s_off[warp];

    // lane-constant weight pointers: col c0+j reads sw[hj*WSTR + i]
    int c0 = 4 * lane;
    const float* pw0 = sw + (c0 / OPHC) * WSTR;
    const float* pw1 = sw + ((c0 + 1) / OPHC) * WSTR;
    const float* pw2 = sw + ((c0 + 2) / OPHC) * WSTR;
    const float* pw3 = sw + ((c0 + 3) / OPHC) * WSTR;
    const char*  hbase = (const char*)g_h + (size_t)c0 * 4;

    unsigned long long acc01 = 0ull, acc23 = 0ull;
    float acc128 = 0.0f;
    float d0 = 0.0f, d1 = 0.0f, d2 = 0.0f;

    for (int base = 0; base < deg; base += ECH) {
        int m = deg - base; if (m > ECH) m = ECH;

        // phase 1: exps + offsets + col128 (lane-strided)
        for (int i = lane; i < m; i += 32) {
            int src = g_csr[s0 + base + i];
            float4 a = *(const float4*)(g_al4 + 4 * src);
            float e0 = __expf(fminf(lrelu(a.x + arn.x), 80.0f));
            float e1 = __expf(fminf(lrelu(a.y + arn.y), 80.0f));
            float e2 = __expf(fminf(lrelu(a.z + arn.z), 80.0f));
            d0 += e0; d1 += e1; d2 += e2;
            sw[i]            = e0;
            sw[WSTR + i]     = e1;
            sw[2 * WSTR + i] = e2;
            soff[i] = src * (LDH * 4);
            acc128 += e2 * g_h[(size_t)src * LDH + 128];
        }
        __syncwarp();

        // phase 2: weighted gather
#pragma unroll 4
        for (int i = 0; i < m; ++i) {
            int off = soff[i];
            float4 hv = *(const float4*)(hbase + off);
            float w0 = pw0[i], w1 = pw1[i], w2 = pw2[i], w3 = pw3[i];
            ffma2(acc01, pack2(w0, w1), pack2(hv.x, hv.y));
            ffma2(acc23, pack2(w2, w3), pack2(hv.z, hv.w));
        }
        __syncwarp();
    }

    // reductions: denominators + col128
#pragma unroll
    for (int off = 16; off; off >>= 1) {
        d0     += __shfl_xor_sync(0xffffffffu, d0, off);
        d1     += __shfl_xor_sync(0xffffffffu, d1, off);
        d2     += __shfl_xor_sync(0xffffffffu, d2, off);
        acc128 += __shfl_xor_sync(0xffffffffu, acc128, off);
    }
    float i0 = 1.0f / (d0 + 1e-16f);
    float i1 = 1.0f / (d1 + 1e-16f);
    float i2 = 1.0f / (d2 + 1e-16f);

    float ix = pick3(i0, i1, i2, c0 / OPHC);
    float iy = pick3(i0, i1, i2, (c0 + 1) / OPHC);
    float iz = pick3(i0, i1, i2, (c0 + 2) / OPHC);
    float iw = pick3(i0, i1, i2, (c0 + 3) / OPHC);

    float ax, ay, az, aw;
    unpack2(acc01, ax, ay);
    unpack2(acc23, az, aw);

    float* op = g_y + (size_t)node * LDH;
    float4 b4 = *(const float4*)(bias + c0);
    float4 o;
    o.x = ax * ix + b4.x;
    o.y = ay * iy + b4.y;
    o.z = az * iz + b4.z;
    o.w = aw * iw + b4.w;
    *(float4*)(op + c0) = o;
    if (lane == 0) op[128] = acc128 * i2 + bias[128];
}

// ---------------- layer-1 GEMM ----------------
__global__ void __launch_bounds__(256, 4) k_gemm_big(
    const float* __restrict__ W, const float* __restrict__ as_,
    const float* __restrict__ ad_, int nrows)
{
    gemm_body((const float*)g_y, W, as_, ad_, nrows, MIDC, LDH, 1);
}

// ---------------- small GEMM (layer 2, CO=6) + fused attention ----------------
__global__ void k_gemm_small(const float* __restrict__ W, const float* __restrict__ as_,
                             const float* __restrict__ ad_, int nrows)
{
    __shared__ float sW[MIDC * 9];
    for (int i = threadIdx.x; i < MIDC * 9; i += blockDim.x) {
        int k = i / 9, c = i - k * 9;
        sW[i] = (c < OUTC) ? W[k * OUTC + c] : 0.0f;
    }
    __syncthreads();

    int lane = threadIdx.x & 31;
    int warp = threadIdx.x >> 5;
    int row  = blockIdx.x * 8 + warp;
    if (row >= nrows) return;

    float acc[6] = {0, 0, 0, 0, 0, 0};
#pragma unroll
    for (int j = 0; j < 5; ++j) {
        int k = lane + 32 * j;
        if (k < MIDC) {
            float xv = lrelu(g_y[(size_t)row * LDH + k]);
            const float* wr = sW + k * 9;
#pragma unroll
            for (int cc = 0; cc < 6; ++cc) acc[cc] += xv * wr[cc];
        }
    }
#pragma unroll
    for (int off = 16; off; off >>= 1)
#pragma unroll
        for (int cc = 0; cc < 6; ++cc)
            acc[cc] += __shfl_xor_sync(0xffffffffu, acc[cc], off);

    if (lane == 0) {
        float al = 0, ar = 0;
        float* hp = g_h + (size_t)row * LDH;
#pragma unroll
        for (int cc = 0; cc < 6; ++cc) {
            al += acc[cc] * as_[cc];
            ar += acc[cc] * ad_[cc];
            hp[cc] = acc[cc];
        }
        *(float4*)(g_al4 + 4 * row) = make_float4(al, 0.0f, 0.0f, 0.0f);
        *(float4*)(g_ar4 + 4 * row) = make_float4(ar, 0.0f, 0.0f, 0.0f);
    }
}

// ---------------- small aggregation (CO=6, 1 head), 4 nodes per warp ----------------
__global__ void k_agg_small(const float* __restrict__ bias, float* __restrict__ dout, int n)
{
    int gw   = (int)((blockIdx.x * blockDim.x + threadIdx.x) >> 5);
    int lane = threadIdx.x & 31;
    int node = gw * 4 + (lane >> 3);
    int sub  = lane & 7;
    if (node >= n) return;

    int s0 = g_offsets[node]     + g_pre[node >> 10];
    int s1 = g_offsets[node + 1] + g_pre[(node + 1) >> 10];
    float arn = g_ar4[4 * node];

    float acc = 0.0f, den = 0.0f;
#pragma unroll 4
    for (int e = s0; e < s1; ++e) {
        int src = g_csr[e];
        float a = g_al4[4 * src];
        float e0 = __expf(fminf(lrelu(a + arn), 80.0f));
        den += e0;
        float hv = (sub < 6) ? g_h[(size_t)src * LDH + sub] : 0.0f;
        acc += e0 * hv;
    }
    if (sub < 6) dout[(size_t)node * OUTC + sub] = acc / (den + 1e-16f) + bias[sub];
}

// ---------------- launcher ----------------
extern "C" void kernel_launch(void* const* d_in, const int* in_sizes, int n_in,
                              void* d_out, int out_size)
{
    const float* x   = (const float*)d_in[0];
    const void*  ei  = d_in[1];
    const float* W0  = (const float*)d_in[2];
    const float* a0s = (const float*)d_in[3];
    const float* a0d = (const float*)d_in[4];
    const float* b0  = (const float*)d_in[5];
    const float* W1  = (const float*)d_in[6];
    const float* a1s = (const float*)d_in[7];
    const float* a1d = (const float*)d_in[8];
    const float* b1  = (const float*)d_in[9];
    const float* W2  = (const float*)d_in[10];
    const float* a2s = (const float*)d_in[11];
    const float* a2d = (const float*)d_in[12];
    const float* b2  = (const float*)d_in[13];

    int N = in_sizes[0] / HIDC;
    int E = in_sizes[1] / 2;

    int tot = E + N;
    int scan_blocks = (N + 1023) / 1024;
    int gemm_grid = (N + 63) / 64;    // 8 warps * 8 rows
    int agg_grid  = (N + 3) / 4;      // 4 warps, 1 node/warp
    int node_grid = (N + 7) / 8;      // 8 warps, 1 node/warp (small kernels)
    int count_blocks = 512;

    // 1: layer-0 GEMM (+attention epilogue) fused with edge counting
    k_gemm0_count<<<gemm_grid + count_blocks, 256>>>(x, W0, a0s, a0d, N, ei, E, gemm_grid);
    // 2: single-pass scan
    k_scan<<<scan_blocks, 1024>>>(scan_blocks, N);
    // 3: CSR fill
    k_fill<<<(tot + 255) / 256, 256>>>(ei, E, N);
    // 4: layer-0 aggregation  <- profiled
    k_agg_big<<<agg_grid, 128>>>(b0, N);
    // 5: layer-1 GEMM
    k_gemm_big<<<gemm_grid, 256>>>(W1, a1s, a1d, N);
    // 6: layer-1 aggregation
    k_agg_big<<<agg_grid, 128>>>(b1, N);
    // 7: layer-2 GEMM
    k_gemm_small<<<node_grid, 256>>>(W2, a2s, a2d, N);
    // 8: layer-2 aggregation
    k_agg_small<<<(N + 31) / 32, 256>>>(b2, (float*)d_out, N);
}